// round 7
// baseline (speedup 1.0000x reference)
#include <cuda_runtime.h>

// Pyramid Givens circuit, n = m = 512, B = 256.
// Layer t in [0,1021): gates (i,i+1) for i ≡ t (mod 2), 0 <= i <= min(t, 1020-t).
// theta index: q=(t+i)/2, tidx = q(q+1)/2 + q - i.
// Gate: a' = c*a + s*b ; b' = c*b - s*a.

#define N_WIRES   512
#define CHUNK_L   6                    // layers per bulk-copy chunk (3 two-layer stages)
#define NCHUNK    172                  // 172 * 6 = 1032 layers (>= 1021; tail identity)
#define T_PAD     (NCHUNK * CHUNK_L)   // 1032
#define LAYER_B   2304                 // 4*32*16 (rot double2) + 32*8 (left float2)
#define CHUNK_B   (CHUNK_L * LAYER_B)  // 13824
#define LEFT_OFF  2048

typedef unsigned long long ull;

// Per layer t (stride LAYER_B bytes):
//   [0,2048): rot cs, entry (r,lane) at r*512 + lane*16, as double2 {c2,s2} (f32x2 payloads)
//     even t, r=0..3: rot (P_2r,P_2r+1): lo gate wire 16L+2r, hi gate 16L+2r+8
//     odd t,  r=0..2: rot (P_2r+1,P_2r+2): lo gate 16L+2r+1, hi gate 16L+2r+9
//     odd t,  r=3:    boundary rot (P7,Q): lo gate 16L+7, hi gate 16L+15
//   [2048,2304): left-gate float2 (c,s) per lane: gate at wire 16L-1 (lane 0 -> identity)
// Inactive gates stored as identity (1,0).
__device__ __align__(128) char g_tab[(size_t)T_PAD * LAYER_B];   // ~2.3 MB

__device__ __forceinline__ float2 cs_of(const float* __restrict__ th, int t, int i) {
    if (t <= 1020 && i >= 0 && i <= t && i <= 1020 - t && (((i ^ t) & 1) == 0)) {
        int q = (t + i) >> 1;
        int tidx = (q * (q + 1)) / 2 + q - i;
        float s, c;
        sincosf(th[tidx], &s, &c);
        return make_float2(c, s);
    }
    return make_float2(1.0f, 0.0f);
}

__global__ void build_cs_kernel(const float* __restrict__ thetas) {
    int t    = blockIdx.x;          // 0..T_PAD-1 (t > 1020 -> identity)
    int r    = threadIdx.x >> 5;    // 0..3
    int lane = threadIdx.x & 31;
    int base = 16 * lane;
    int ilo, ihi;
    if ((t & 1) == 0)      { ilo = base + 2 * r;     ihi = ilo + 8; }
    else if (r < 3)        { ilo = base + 2 * r + 1; ihi = ilo + 8; }
    else                   { ilo = base + 7;         ihi = base + 15; }
    float2 a = cs_of(thetas, t, ilo);
    float2 b = cs_of(thetas, t, ihi);
    float2* dst = reinterpret_cast<float2*>(g_tab + (size_t)t * LAYER_B + r * 512 + lane * 16);
    dst[0] = make_float2(a.x, b.x);   // c2 = (c_lo, c_hi)
    dst[1] = make_float2(a.y, b.y);   // s2 = (s_lo, s_hi)
    if (r == 3) {
        float2 lf = (lane == 0) ? make_float2(1.0f, 0.0f) : cs_of(thetas, t, base - 1);
        *reinterpret_cast<float2*>(g_tab + (size_t)t * LAYER_B + LEFT_OFF + lane * 8) = lf;
    }
}

// ---- f32x2 helpers ----
__device__ __forceinline__ ull mul2(ull a, ull b) {
    ull d; asm("mul.rn.f32x2 %0, %1, %2;" : "=l"(d) : "l"(a), "l"(b)); return d;
}
__device__ __forceinline__ ull fma2(ull a, ull b, ull c) {
    ull d; asm("fma.rn.f32x2 %0, %1, %2, %3;" : "=l"(d) : "l"(a), "l"(b), "l"(c)); return d;
}
__device__ __forceinline__ float lo_f(ull p) {
    float lo, hi; asm("mov.b64 {%0, %1}, %2;" : "=f"(lo), "=f"(hi) : "l"(p)); return lo;
}
__device__ __forceinline__ float hi_f(ull p) {
    float lo, hi; asm("mov.b64 {%0, %1}, %2;" : "=f"(lo), "=f"(hi) : "l"(p)); return hi;
}
__device__ __forceinline__ ull pk(float lo, float hi) {
    ull d; asm("mov.b64 %0, {%1, %2};" : "=l"(d) : "f"(lo), "f"(hi)); return d;
}

#define SGNMASK 0x8000000080000000ULL
#define FULLM   0xffffffffu

__device__ __forceinline__ void rotp(ull& a, ull& b, double2 cs) {
    ull c2 = __double_as_longlong(cs.x);
    ull s2 = __double_as_longlong(cs.y);
    ull t1 = mul2(s2, b);
    ull na = fma2(c2, a, t1);
    ull t2 = mul2(s2, a) ^ SGNMASK;      // -s*a
    b = fma2(c2, b, t2);
    a = na;
}

// ---- bulk-copy / mbarrier helpers ----
__device__ __forceinline__ unsigned s2u(const void* p) {
    return (unsigned)__cvta_generic_to_shared(p);
}
__device__ __forceinline__ void mbar_init(unsigned mbar, unsigned cnt) {
    asm volatile("mbarrier.init.shared.b64 [%0], %1;" :: "r"(mbar), "r"(cnt) : "memory");
}
__device__ __forceinline__ void mbar_expect_tx(unsigned mbar, unsigned bytes) {
    asm volatile("mbarrier.arrive.expect_tx.shared.b64 _, [%0], %1;"
                 :: "r"(mbar), "r"(bytes) : "memory");
}
__device__ __forceinline__ void bulk_g2s(unsigned dst, const void* src, unsigned bytes,
                                         unsigned mbar) {
    asm volatile("cp.async.bulk.shared::cluster.global.mbarrier::complete_tx::bytes "
                 "[%0], [%1], %2, [%3];"
                 :: "r"(dst), "l"(src), "r"(bytes), "r"(mbar) : "memory");
}
__device__ __forceinline__ void mbar_wait(unsigned mbar, unsigned parity) {
    unsigned done;
    asm volatile(
        "{\n\t.reg .pred p;\n\t"
        "mbarrier.try_wait.parity.acquire.cta.shared::cta.b64 p, [%1], %2;\n\t"
        "selp.b32 %0, 1, 0, p;\n\t}"
        : "=r"(done) : "r"(mbar), "r"(parity) : "memory");
    if (!done) {
        asm volatile(
            "{\n\t.reg .pred P1;\n\t"
            "WL_%=:\n\t"
            "mbarrier.try_wait.parity.acquire.cta.shared::cta.b64 P1, [%0], %1, 0x989680;\n\t"
            "@P1 bra.uni WD_%=;\n\t"
            "bra.uni WL_%=;\n\t"
            "WD_%=:\n\t}"
            :: "r"(mbar), "r"(parity) : "memory");
    }
}
__device__ __forceinline__ void fence_async_shared() {
    asm volatile("fence.proxy.async.shared::cta;" ::: "memory");
}

// Two-layer stage body for one row's state P[8] (even layer + odd layer).
__device__ __forceinline__ void stage_row(ull* P,
                                          double2 E0, double2 E1, double2 E2, double2 E3,
                                          double2 O0, double2 O1, double2 O2, double2 O3,
                                          float2 LF, int lane)
{
    // ---- even layer ----
    rotp(P[0], P[1], E0);
    rotp(P[2], P[3], E1);
    rotp(P[4], P[5], E2);
    rotp(P[6], P[7], E3);
    // ---- odd layer ----
    float v16  = __shfl_down_sync(FULLM, lo_f(P[0]), 1); // right nbr v0
    float lv15 = __shfl_up_sync  (FULLM, hi_f(P[7]), 1); // left  nbr v15
    rotp(P[1], P[2], O0);
    rotp(P[3], P[4], O1);
    rotp(P[5], P[6], O2);
    ull Q = pk(hi_f(P[0]), v16);          // (v8, v16)
    rotp(P[7], Q, O3);                    // boundary: (v7,v15) x (v8,v16)
    float nv0 = fmaf(LF.x, lo_f(P[0]), -(LF.y * lv15));  // left gate, redundant
    P[0] = pk(nv0, lo_f(Q));              // (new v0, new v8)
}

// One warp per CTA handling TWO batch rows (ILP): rows 2b and 2b+1.
// cs table streamed global->smem via single-thread cp.async.bulk (3 buffers),
// consumed once per stage and applied to both rows.
__global__ void __launch_bounds__(32, 1) apply_kernel(
    const float* __restrict__ x,
    const float* __restrict__ bias,
    float* __restrict__ out)
{
    __shared__ __align__(128) char sbuf[3][CHUNK_B];   // 41472 B
    __shared__ __align__(8) unsigned long long mbar[3];

    const int tid  = threadIdx.x;
    const int lane = tid & 31;
    const int row0 = blockIdx.x * 2;

    if (tid == 0) {
        mbar_init(s2u(&mbar[0]), 1);
        mbar_init(s2u(&mbar[1]), 1);
        mbar_init(s2u(&mbar[2]), 1);
    }

    // Load both rows, pack P[k] = (v_k, v_{k+8}); lane owns wires [16L, 16L+15]
    ull PA[8], PB[8];
    {
        const float4* xa = reinterpret_cast<const float4*>(x + (size_t)row0 * N_WIRES) + lane * 4;
        const float4* xb = reinterpret_cast<const float4*>(x + (size_t)(row0 + 1) * N_WIRES) + lane * 4;
        float va[16], vb[16];
        #pragma unroll
        for (int j = 0; j < 4; ++j) {
            float4 fa = xa[j], fb = xb[j];
            va[4*j+0] = fa.x; va[4*j+1] = fa.y; va[4*j+2] = fa.z; va[4*j+3] = fa.w;
            vb[4*j+0] = fb.x; vb[4*j+1] = fb.y; vb[4*j+2] = fb.z; vb[4*j+3] = fb.w;
        }
        #pragma unroll
        for (int k = 0; k < 8; ++k) { PA[k] = pk(va[k], va[k+8]); PB[k] = pk(vb[k], vb[k+8]); }
    }

    __syncwarp();    // mbar inits visible (same warp)

    // prologue: issue chunks 0,1,2
    if (tid == 0) {
        #pragma unroll
        for (int pc = 0; pc < 3; ++pc) {
            unsigned mb = s2u(&mbar[pc]);
            mbar_expect_tx(mb, CHUNK_B);
            bulk_g2s(s2u(&sbuf[pc][0]), g_tab + (size_t)pc * CHUNK_B, CHUNK_B, mb);
        }
    }

    int rb = 0;           // buffer holding chunk c (rb == c % 3)
    #pragma unroll 1
    for (int c = 0; c < NCHUNK; ++c) {
        mbar_wait(s2u(&mbar[rb]), (unsigned)((c / 3) & 1));

        const char* cb = sbuf[rb];
        #pragma unroll
        for (int s = 0; s < CHUNK_L / 2; ++s) {
            const char* le = cb + (2 * s) * LAYER_B;
            const char* lo = le + LAYER_B;
            double2 E0 = *reinterpret_cast<const double2*>(le +    0 + lane * 16);
            double2 E1 = *reinterpret_cast<const double2*>(le +  512 + lane * 16);
            double2 E2 = *reinterpret_cast<const double2*>(le + 1024 + lane * 16);
            double2 E3 = *reinterpret_cast<const double2*>(le + 1536 + lane * 16);
            double2 O0 = *reinterpret_cast<const double2*>(lo +    0 + lane * 16);
            double2 O1 = *reinterpret_cast<const double2*>(lo +  512 + lane * 16);
            double2 O2 = *reinterpret_cast<const double2*>(lo + 1024 + lane * 16);
            double2 O3 = *reinterpret_cast<const double2*>(lo + 1536 + lane * 16);
            float2  LF = *reinterpret_cast<const float2*>(lo + LEFT_OFF + lane * 8);

            stage_row(PA, E0, E1, E2, E3, O0, O1, O2, O3, LF, lane);
            stage_row(PB, E0, E1, E2, E3, O0, O1, O2, O3, LF, lane);
        }

        __syncwarp();   // all lanes done reading buffer rb
        if (tid == 0 && c + 3 < NCHUNK) {
            fence_async_shared();
            unsigned mb = s2u(&mbar[rb]);
            mbar_expect_tx(mb, CHUNK_B);
            bulk_g2s(s2u(&sbuf[rb][0]), g_tab + (size_t)(c + 3) * CHUNK_B, CHUNK_B, mb);
        }

        rb = (rb == 2) ? 0 : rb + 1;
    }

    // store + bias: wires 16L+k (lo halves), 16L+8+k (hi halves)
    {
        const float4* bb = reinterpret_cast<const float4*>(bias) + lane * 4;
        float4 b0 = bb[0], b1 = bb[1], b2 = bb[2], b3 = bb[3];
        #pragma unroll
        for (int rsel = 0; rsel < 2; ++rsel) {
            ull* P = rsel ? PB : PA;
            float4* outr = reinterpret_cast<float4*>(out + (size_t)(row0 + rsel) * N_WIRES) + lane * 4;
            float4 o0, o1, o2, o3;
            o0.x = lo_f(P[0]) + b0.x; o0.y = lo_f(P[1]) + b0.y;
            o0.z = lo_f(P[2]) + b0.z; o0.w = lo_f(P[3]) + b0.w;
            o1.x = lo_f(P[4]) + b1.x; o1.y = lo_f(P[5]) + b1.y;
            o1.z = lo_f(P[6]) + b1.z; o1.w = lo_f(P[7]) + b1.w;
            o2.x = hi_f(P[0]) + b2.x; o2.y = hi_f(P[1]) + b2.y;
            o2.z = hi_f(P[2]) + b2.z; o2.w = hi_f(P[3]) + b2.w;
            o3.x = hi_f(P[4]) + b3.x; o3.y = hi_f(P[5]) + b3.y;
            o3.z = hi_f(P[6]) + b3.z; o3.w = hi_f(P[7]) + b3.w;
            outr[0] = o0; outr[1] = o1; outr[2] = o2; outr[3] = o3;
        }
    }
}

extern "C" void kernel_launch(void* const* d_in, const int* in_sizes, int n_in,
                              void* d_out, int out_size) {
    const float* x      = (const float*)d_in[0];
    const float* thetas = (const float*)d_in[1];
    const float* bias   = (const float*)d_in[2];
    float* out = (float*)d_out;

    build_cs_kernel<<<T_PAD, 128>>>(thetas);

    int B = in_sizes[0] / N_WIRES;   // 256
    apply_kernel<<<B / 2, 32>>>(x, bias, out);
}

// round 8
// speedup vs baseline: 1.7010x; 1.7010x over previous
#include <cuda_runtime.h>

// Pyramid Givens circuit, n = m = 512, B = 256.
// Layer t in [0,1021): gates (i,i+1) for i ≡ t (mod 2), 0 <= i <= min(t, 1020-t).
// theta index: q=(t+i)/2, tidx = q(q+1)/2 + q - i.
// Gate: a' = c*a + s*b ; b' = c*b - s*a.

#define N_WIRES   512
#define CHUNK_L   12                   // layers per bulk-copy chunk (6 two-layer stages)
#define NCHUNK    86                   // 86 * 12 = 1032 layers (>= 1021; tail identity)
#define T_PAD     (NCHUNK * CHUNK_L)   // 1032
#define LAYER_B   2304                 // 4*32*16 (rot double2) + 32*8 (left float2)
#define CHUNK_B   (CHUNK_L * LAYER_B)  // 27648
#define LEFT_OFF  2048

typedef unsigned long long ull;

// Per layer t (stride LAYER_B bytes):
//   [0,2048): rot cs, entry (r,lane) at r*512 + lane*16, as double2 {c2,s2} (f32x2 payloads)
//     even t, r=0..3: rot (P_2r,P_2r+1): lo gate wire 16L+2r, hi gate 16L+2r+8
//     odd t,  r=0..2: rot (P_2r+1,P_2r+2): lo gate 16L+2r+1, hi gate 16L+2r+9
//     odd t,  r=3:    boundary rot (P7,Q): lo gate 16L+7, hi gate 16L+15
//   [2048,2304): left-gate float2 (c,s) per lane: gate at wire 16L-1 (lane 0 -> identity)
// Inactive gates stored as identity (1,0).
__device__ __align__(128) char g_tab[(size_t)T_PAD * LAYER_B];   // ~2.3 MB

__device__ __forceinline__ float2 cs_of(const float* __restrict__ th, int t, int i) {
    if (t <= 1020 && i >= 0 && i <= t && i <= 1020 - t && (((i ^ t) & 1) == 0)) {
        int q = (t + i) >> 1;
        int tidx = (q * (q + 1)) / 2 + q - i;
        float s, c;
        sincosf(th[tidx], &s, &c);
        return make_float2(c, s);
    }
    return make_float2(1.0f, 0.0f);
}

__global__ void build_cs_kernel(const float* __restrict__ thetas) {
    int t    = blockIdx.x;          // 0..T_PAD-1 (t > 1020 -> identity)
    int r    = threadIdx.x >> 5;    // 0..3
    int lane = threadIdx.x & 31;
    int base = 16 * lane;
    int ilo, ihi;
    if ((t & 1) == 0)      { ilo = base + 2 * r;     ihi = ilo + 8; }
    else if (r < 3)        { ilo = base + 2 * r + 1; ihi = ilo + 8; }
    else                   { ilo = base + 7;         ihi = base + 15; }
    float2 a = cs_of(thetas, t, ilo);
    float2 b = cs_of(thetas, t, ihi);
    float2* dst = reinterpret_cast<float2*>(g_tab + (size_t)t * LAYER_B + r * 512 + lane * 16);
    dst[0] = make_float2(a.x, b.x);   // c2 = (c_lo, c_hi)
    dst[1] = make_float2(a.y, b.y);   // s2 = (s_lo, s_hi)
    if (r == 3) {
        float2 lf = (lane == 0) ? make_float2(1.0f, 0.0f) : cs_of(thetas, t, base - 1);
        *reinterpret_cast<float2*>(g_tab + (size_t)t * LAYER_B + LEFT_OFF + lane * 8) = lf;
    }
}

// ---- f32x2 helpers ----
__device__ __forceinline__ ull mul2(ull a, ull b) {
    ull d; asm("mul.rn.f32x2 %0, %1, %2;" : "=l"(d) : "l"(a), "l"(b)); return d;
}
__device__ __forceinline__ ull fma2(ull a, ull b, ull c) {
    ull d; asm("fma.rn.f32x2 %0, %1, %2, %3;" : "=l"(d) : "l"(a), "l"(b), "l"(c)); return d;
}
__device__ __forceinline__ float lo_f(ull p) {
    float lo, hi; asm("mov.b64 {%0, %1}, %2;" : "=f"(lo), "=f"(hi) : "l"(p)); return lo;
}
__device__ __forceinline__ float hi_f(ull p) {
    float lo, hi; asm("mov.b64 {%0, %1}, %2;" : "=f"(lo), "=f"(hi) : "l"(p)); return hi;
}
__device__ __forceinline__ ull pk(float lo, float hi) {
    ull d; asm("mov.b64 %0, {%1, %2};" : "=l"(d) : "f"(lo), "f"(hi)); return d;
}

#define SGNMASK 0x8000000080000000ULL
#define FULLM   0xffffffffu

// Packed Givens with pre-negated sine: a' = c*a + s*b ; b' = c*b + ns*a (ns = -s)
__device__ __forceinline__ void rotp2(ull& a, ull& b, ull c2, ull s2, ull ns2) {
    ull t1 = mul2(s2, b);
    ull na = fma2(c2, a, t1);
    ull t2 = mul2(ns2, a);
    b = fma2(c2, b, t2);
    a = na;
}

// ---- bulk-copy / mbarrier helpers ----
__device__ __forceinline__ unsigned s2u(const void* p) {
    return (unsigned)__cvta_generic_to_shared(p);
}
__device__ __forceinline__ void mbar_init(unsigned mbar, unsigned cnt) {
    asm volatile("mbarrier.init.shared.b64 [%0], %1;" :: "r"(mbar), "r"(cnt) : "memory");
}
__device__ __forceinline__ void mbar_expect_tx(unsigned mbar, unsigned bytes) {
    asm volatile("mbarrier.arrive.expect_tx.shared.b64 _, [%0], %1;"
                 :: "r"(mbar), "r"(bytes) : "memory");
}
__device__ __forceinline__ void bulk_g2s(unsigned dst, const void* src, unsigned bytes,
                                         unsigned mbar) {
    asm volatile("cp.async.bulk.shared::cluster.global.mbarrier::complete_tx::bytes "
                 "[%0], [%1], %2, [%3];"
                 :: "r"(dst), "l"(src), "r"(bytes), "r"(mbar) : "memory");
}
__device__ __forceinline__ void mbar_wait(unsigned mbar, unsigned parity) {
    unsigned done;
    asm volatile(
        "{\n\t.reg .pred p;\n\t"
        "mbarrier.try_wait.parity.acquire.cta.shared::cta.b64 p, [%1], %2;\n\t"
        "selp.b32 %0, 1, 0, p;\n\t}"
        : "=r"(done) : "r"(mbar), "r"(parity) : "memory");
    if (!done) {
        asm volatile(
            "{\n\t.reg .pred P1;\n\t"
            "WL_%=:\n\t"
            "mbarrier.try_wait.parity.acquire.cta.shared::cta.b64 P1, [%0], %1, 0x989680;\n\t"
            "@P1 bra.uni WD_%=;\n\t"
            "bra.uni WL_%=;\n\t"
            "WD_%=:\n\t}"
            :: "r"(mbar), "r"(parity) : "memory");
    }
}
__device__ __forceinline__ void fence_async_shared() {
    asm volatile("fence.proxy.async.shared::cta;" ::: "memory");
}

// Stage coefficient set, held in registers (ping-pong prefetch).
struct Coef {
    ull Ec[4], Es[4], Oc[4], Os[4];
    float lfc, lfs;
};

__device__ __forceinline__ void load_stage(Coef& d, const char* le, int lane) {
    const char* lo = le + LAYER_B;
    #pragma unroll
    for (int j = 0; j < 4; ++j) {
        double2 e = *reinterpret_cast<const double2*>(le + j * 512 + lane * 16);
        d.Ec[j] = __double_as_longlong(e.x);
        d.Es[j] = __double_as_longlong(e.y);
        double2 o = *reinterpret_cast<const double2*>(lo + j * 512 + lane * 16);
        d.Oc[j] = __double_as_longlong(o.x);
        d.Os[j] = __double_as_longlong(o.y);
    }
    float2 lf = *reinterpret_cast<const float2*>(lo + LEFT_OFF + lane * 8);
    d.lfc = lf.x;
    d.lfs = lf.y;
}

// One warp per batch row, 2 warps per CTA. cs table streamed global->smem via
// single-thread cp.async.bulk (3 buffers, 3 chunks in flight); per-stage
// coefficients register-prefetched one stage ahead (intra-chunk).
__global__ void __launch_bounds__(64, 1) apply_kernel(
    const float* __restrict__ x,
    const float* __restrict__ bias,
    float* __restrict__ out)
{
    extern __shared__ __align__(128) char sbuf[];        // 3 * CHUNK_B dynamic
    __shared__ __align__(8) unsigned long long mbar[3];

    const int tid  = threadIdx.x;
    const int lane = tid & 31;
    const int row  = blockIdx.x * 2 + (tid >> 5);

    if (tid == 0) {
        mbar_init(s2u(&mbar[0]), 1);
        mbar_init(s2u(&mbar[1]), 1);
        mbar_init(s2u(&mbar[2]), 1);
    }

    // Load row, pack P[k] = (v_k, v_{k+8}); lane owns wires [16L, 16L+15]
    ull P[8];
    {
        float v[16];
        const float4* xr = reinterpret_cast<const float4*>(x + (size_t)row * N_WIRES) + lane * 4;
        #pragma unroll
        for (int j = 0; j < 4; ++j) {
            float4 f = xr[j];
            v[4*j+0] = f.x; v[4*j+1] = f.y; v[4*j+2] = f.z; v[4*j+3] = f.w;
        }
        #pragma unroll
        for (int k = 0; k < 8; ++k) P[k] = pk(v[k], v[k + 8]);
    }

    __syncthreads();    // mbar inits visible

    // prologue: issue chunks 0,1,2
    if (tid == 0) {
        #pragma unroll
        for (int pc = 0; pc < 3; ++pc) {
            unsigned mb = s2u(&mbar[pc]);
            mbar_expect_tx(mb, CHUNK_B);
            bulk_g2s(s2u(sbuf + pc * CHUNK_B), g_tab + (size_t)pc * CHUNK_B, CHUNK_B, mb);
        }
    }

    Coef st[2];
    int rb = 0;           // buffer holding chunk c (rb == c % 3)
    #pragma unroll 1
    for (int c = 0; c < NCHUNK; ++c) {
        mbar_wait(s2u(&mbar[rb]), (unsigned)((c / 3) & 1));

        const char* cb = sbuf + rb * CHUNK_B;
        load_stage(st[0], cb, lane);          // stage 0 (exposed once per chunk)

        #pragma unroll
        for (int s = 0; s < CHUNK_L / 2; ++s) {
            if (s + 1 < CHUNK_L / 2)
                load_stage(st[(s + 1) & 1], cb + (2 * (s + 1)) * LAYER_B, lane);
            Coef& C = st[s & 1];

            // off-chain precomputation (operands already register-resident)
            ull nEs[4], nOs[4];
            #pragma unroll
            for (int j = 0; j < 4; ++j) { nEs[j] = C.Es[j] ^ SGNMASK; nOs[j] = C.Os[j] ^ SGNMASK; }
            float nlfs = -C.lfs;

            // ---- even layer: boundary-feeding rots first ----
            rotp2(P[0], P[1], C.Ec[0], C.Es[0], nEs[0]);
            rotp2(P[6], P[7], C.Ec[3], C.Es[3], nEs[3]);
            float pv0  = lo_f(P[0]);                 // post-even v0
            float pv15 = hi_f(P[7]);                 // post-even v15
            float v16  = __shfl_down_sync(FULLM, pv0, 1);   // right nbr v0
            float lv15 = __shfl_up_sync  (FULLM, pv15, 1);  // left  nbr v15
            float base0 = C.lfc * pv0;               // LF.x * v0 (early)
            rotp2(P[2], P[3], C.Ec[1], C.Es[1], nEs[1]);
            rotp2(P[4], P[5], C.Ec[2], C.Es[2], nEs[2]);

            // ---- odd layer ----
            rotp2(P[1], P[2], C.Oc[0], C.Os[0], nOs[0]);
            rotp2(P[3], P[4], C.Oc[1], C.Os[1], nOs[1]);
            rotp2(P[5], P[6], C.Oc[2], C.Os[2], nOs[2]);
            ull Q = pk(hi_f(P[0]), v16);             // (v8, v16)
            rotp2(P[7], Q, C.Oc[3], C.Os[3], nOs[3]);  // boundary: (v7,v15)x(v8,v16)
            float nv0 = fmaf(nlfs, lv15, base0);     // left gate (redundant); lane0 id
            P[0] = pk(nv0, lo_f(Q));                 // (new v0, new v8)
        }

        __syncthreads();   // both warps done reading buffer rb
        if (tid == 0 && c + 3 < NCHUNK) {
            fence_async_shared();
            unsigned mb = s2u(&mbar[rb]);
            mbar_expect_tx(mb, CHUNK_B);
            bulk_g2s(s2u(sbuf + rb * CHUNK_B), g_tab + (size_t)(c + 3) * CHUNK_B, CHUNK_B, mb);
        }

        rb = (rb == 2) ? 0 : rb + 1;
    }

    // store + bias: wires 16L+k (lo halves), 16L+8+k (hi halves)
    {
        const float4* bb   = reinterpret_cast<const float4*>(bias) + lane * 4;
        float4*       outr = reinterpret_cast<float4*>(out + (size_t)row * N_WIRES) + lane * 4;
        float4 b0 = bb[0], b1 = bb[1], b2 = bb[2], b3 = bb[3];
        float4 o0, o1, o2, o3;
        o0.x = lo_f(P[0]) + b0.x; o0.y = lo_f(P[1]) + b0.y;
        o0.z = lo_f(P[2]) + b0.z; o0.w = lo_f(P[3]) + b0.w;
        o1.x = lo_f(P[4]) + b1.x; o1.y = lo_f(P[5]) + b1.y;
        o1.z = lo_f(P[6]) + b1.z; o1.w = lo_f(P[7]) + b1.w;
        o2.x = hi_f(P[0]) + b2.x; o2.y = hi_f(P[1]) + b2.y;
        o2.z = hi_f(P[2]) + b2.z; o2.w = hi_f(P[3]) + b2.w;
        o3.x = hi_f(P[4]) + b3.x; o3.y = hi_f(P[5]) + b3.y;
        o3.z = hi_f(P[6]) + b3.z; o3.w = hi_f(P[7]) + b3.w;
        outr[0] = o0; outr[1] = o1; outr[2] = o2; outr[3] = o3;
    }
}

extern "C" void kernel_launch(void* const* d_in, const int* in_sizes, int n_in,
                              void* d_out, int out_size) {
    const float* x      = (const float*)d_in[0];
    const float* thetas = (const float*)d_in[1];
    const float* bias   = (const float*)d_in[2];
    float* out = (float*)d_out;

    build_cs_kernel<<<T_PAD, 128>>>(thetas);

    cudaFuncSetAttribute(apply_kernel,
                         cudaFuncAttributeMaxDynamicSharedMemorySize, 3 * CHUNK_B);

    int B = in_sizes[0] / N_WIRES;   // 256
    apply_kernel<<<B / 2, 64, 3 * CHUNK_B>>>(x, bias, out);
}